// round 1
// baseline (speedup 1.0000x reference)
#include <cuda_runtime.h>
#include <math.h>

// ---------------- problem constants ----------------
#define NN   50000
#define NE   1600000
#define EPAD (NE + NN)        // edges + self loops
#define NF   512
#define H1   8
#define C1   16
#define HC1  128              // H1*C1
#define C2   16

// ---------------- scratch (device globals; no allocation allowed) ----------------
__device__ float g_h1[NN * HC1];
__device__ float g_as1[NN * H1];
__device__ float g_ad1[NN * H1];
__device__ float g_amax1[NN * H1];
__device__ float g_den1[NN * H1];
__device__ float g_alpha1[EPAD * H1];
__device__ float g_out1[NN * HC1];
__device__ float g_h2[NN * C2];
__device__ float g_as2[NN];
__device__ float g_ad2[NN];
__device__ float g_amax2[NN];
__device__ float g_den2[NN];
__device__ float g_alpha2[EPAD];
__device__ float g_out2[NN * C2];

// ---------------- helpers ----------------
__device__ __forceinline__ void atomicMaxF(float* addr, float v) {
    // standard monotone bit trick; buffer must be initialized to -inf
    if (v >= 0.f) atomicMax((int*)addr, __float_as_int(v));
    else          atomicMin((unsigned int*)addr, __float_as_uint(v));
}

__global__ void fill_kernel(float* p, float v, int n) {
    int i = blockIdx.x * blockDim.x + threadIdx.x;
    if (i < n) p[i] = v;
}

// ---------------- GEMM: C[M,N] = A[M,K] * B[N,K]^T  (both K-contiguous, "NT") ----------------
#define BM 64
#define BN 64
#define BK 16

__global__ void gemm_nt(const float* __restrict__ A, const float* __restrict__ B,
                        float* __restrict__ C, int M, int Nn, int K) {
    __shared__ float As[BM][BK + 1];
    __shared__ float Bs[BN][BK + 1];
    int tid = threadIdx.x;
    int tx = tid & 15, ty = tid >> 4;          // 16x16 thread grid
    int m0 = blockIdx.y * BM, n0 = blockIdx.x * BN;
    int lr = tid >> 2;                          // 0..63 : row of tile
    int lc = (tid & 3) * 4;                     // 0,4,8,12 : k-offset (float4)

    float acc[4][4];
    #pragma unroll
    for (int i = 0; i < 4; i++)
        #pragma unroll
        for (int j = 0; j < 4; j++) acc[i][j] = 0.f;

    for (int k0 = 0; k0 < K; k0 += BK) {
        int am = m0 + lr;
        if (am < M) {
            float4 v = *reinterpret_cast<const float4*>(&A[(size_t)am * K + k0 + lc]);
            As[lr][lc] = v.x; As[lr][lc + 1] = v.y; As[lr][lc + 2] = v.z; As[lr][lc + 3] = v.w;
        } else {
            As[lr][lc] = 0.f; As[lr][lc + 1] = 0.f; As[lr][lc + 2] = 0.f; As[lr][lc + 3] = 0.f;
        }
        int bn = n0 + lr;
        if (bn < Nn) {
            float4 v = *reinterpret_cast<const float4*>(&B[(size_t)bn * K + k0 + lc]);
            Bs[lr][lc] = v.x; Bs[lr][lc + 1] = v.y; Bs[lr][lc + 2] = v.z; Bs[lr][lc + 3] = v.w;
        } else {
            Bs[lr][lc] = 0.f; Bs[lr][lc + 1] = 0.f; Bs[lr][lc + 2] = 0.f; Bs[lr][lc + 3] = 0.f;
        }
        __syncthreads();
        #pragma unroll
        for (int k = 0; k < BK; k++) {
            float a[4], b[4];
            #pragma unroll
            for (int i = 0; i < 4; i++) a[i] = As[ty * 4 + i][k];
            #pragma unroll
            for (int j = 0; j < 4; j++) b[j] = Bs[tx * 4 + j][k];
            #pragma unroll
            for (int i = 0; i < 4; i++)
                #pragma unroll
                for (int j = 0; j < 4; j++) acc[i][j] += a[i] * b[j];
        }
        __syncthreads();
    }
    #pragma unroll
    for (int i = 0; i < 4; i++) {
        int m = m0 + ty * 4 + i;
        if (m >= M) continue;
        #pragma unroll
        for (int j = 0; j < 4; j++) {
            int n = n0 + tx * 4 + j;
            if (n < Nn) C[(size_t)m * Nn + n] = acc[i][j];
        }
    }
}

// ---------------- per-node attention coefficients ----------------
// a_src[n,h] = sum_c h[n,h,c]*att_src[h,c] ;  a_dst likewise
__global__ void att_kernel(const float* __restrict__ h, const float* __restrict__ att_s,
                           const float* __restrict__ att_d, float* __restrict__ as_,
                           float* __restrict__ ad_, int N, int H, int C) {
    int idx = blockIdx.x * blockDim.x + threadIdx.x;
    if (idx >= N * H) return;
    int n = idx / H, hh = idx - n * H;
    const float* hp = h + ((size_t)n * H + hh) * C;
    float s = 0.f, d = 0.f;
    for (int c = 0; c < C; c++) {
        float v = hp[c];
        s += v * att_s[hh * C + c];
        d += v * att_d[hh * C + c];
    }
    as_[idx] = s;
    ad_[idx] = d;
}

// ---------------- edge pass 1: leaky-relu score + segment max ----------------
__global__ void edge_max(const int* __restrict__ ei, const float* __restrict__ as_,
                         const float* __restrict__ ad_, float* __restrict__ alpha,
                         float* __restrict__ amax, int E, int Ntot, int H) {
    int idx = blockIdx.x * blockDim.x + threadIdx.x;
    int tot = (E + Ntot) * H;
    if (idx >= tot) return;
    int e = idx / H, h = idx - e * H;
    int s, d;
    if (e < E) { s = ei[e]; d = ei[E + e]; } else { s = d = e - E; }
    float v = as_[s * H + h] + ad_[d * H + h];
    v = v > 0.f ? v : 0.2f * v;          // leaky_relu, slope 0.2
    alpha[idx] = v;
    atomicMaxF(&amax[d * H + h], v);
}

// ---------------- edge pass 2: exp + segment sum ----------------
__global__ void edge_exp(const int* __restrict__ ei, float* __restrict__ alpha,
                         const float* __restrict__ amax, float* __restrict__ den,
                         int E, int Ntot, int H) {
    int idx = blockIdx.x * blockDim.x + threadIdx.x;
    int tot = (E + Ntot) * H;
    if (idx >= tot) return;
    int e = idx / H, h = idx - e * H;
    int d;
    if (e < E) d = ei[E + e]; else d = e - E;
    float v = expf(alpha[idx] - amax[d * H + h]);
    alpha[idx] = v;
    atomicAdd(&den[d * H + h], v);
}

// ---------------- edge pass 3: normalize + weighted aggregate ----------------
__global__ void edge_agg(const int* __restrict__ ei, const float* __restrict__ alpha,
                         const float* __restrict__ den, const float* __restrict__ hsrc,
                         float* __restrict__ out, int E, int Ntot, int H, int C) {
    int idx = blockIdx.x * blockDim.x + threadIdx.x;
    int tot = (E + Ntot) * H;
    if (idx >= tot) return;
    int e = idx / H, h = idx - e * H;
    int s, d;
    if (e < E) { s = ei[e]; d = ei[E + e]; } else { s = d = e - E; }
    float w = alpha[idx] / (den[d * H + h] + 1e-16f);
    const float* hp = hsrc + ((size_t)s * H + h) * C;
    float* op = out + ((size_t)d * H + h) * C;
    for (int c = 0; c < C; c++) atomicAdd(&op[c], w * hp[c]);
}

// ---------------- bias + ELU ----------------
__global__ void elu_bias(float* __restrict__ x, const float* __restrict__ b, int n, int F) {
    int i = blockIdx.x * blockDim.x + threadIdx.x;
    if (i >= n) return;
    float v = x[i] + b[i % F];
    x[i] = v > 0.f ? v : expm1f(v);
}

// ---------------- final bias + log_softmax ----------------
__global__ void final_lsm(const float* __restrict__ in, const float* __restrict__ b,
                          float* __restrict__ out, int N) {
    int n = blockIdx.x * blockDim.x + threadIdx.x;
    if (n >= N) return;
    float v[C2];
    float m = -INFINITY;
    #pragma unroll
    for (int c = 0; c < C2; c++) {
        v[c] = in[(size_t)n * C2 + c] + b[c];
        m = fmaxf(m, v[c]);
    }
    float s = 0.f;
    #pragma unroll
    for (int c = 0; c < C2; c++) s += expf(v[c] - m);
    float l = logf(s);
    #pragma unroll
    for (int c = 0; c < C2; c++) out[(size_t)n * C2 + c] = v[c] - m - l;
}

// ---------------- launch ----------------
extern "C" void kernel_launch(void* const* d_in, const int* in_sizes, int n_in,
                              void* d_out, int out_size) {
    const float* x   = (const float*)d_in[0];
    const int*   ei  = (const int*)d_in[1];
    const float* W1  = (const float*)d_in[2];
    const float* at1s = (const float*)d_in[3];
    const float* at1d = (const float*)d_in[4];
    const float* b1  = (const float*)d_in[5];
    const float* W2  = (const float*)d_in[6];
    const float* at2s = (const float*)d_in[7];
    const float* at2d = (const float*)d_in[8];
    const float* b2  = (const float*)d_in[9];
    float* out = (float*)d_out;

    int E = in_sizes[1] / 2;
    int EP = E + NN;

    static float *p_h1 = nullptr, *p_as1, *p_ad1, *p_amax1, *p_den1, *p_alpha1, *p_out1,
                 *p_h2, *p_as2, *p_ad2, *p_amax2, *p_den2, *p_alpha2, *p_out2;
    if (!p_h1) {
        cudaGetSymbolAddress((void**)&p_h1, g_h1);
        cudaGetSymbolAddress((void**)&p_as1, g_as1);
        cudaGetSymbolAddress((void**)&p_ad1, g_ad1);
        cudaGetSymbolAddress((void**)&p_amax1, g_amax1);
        cudaGetSymbolAddress((void**)&p_den1, g_den1);
        cudaGetSymbolAddress((void**)&p_alpha1, g_alpha1);
        cudaGetSymbolAddress((void**)&p_out1, g_out1);
        cudaGetSymbolAddress((void**)&p_h2, g_h2);
        cudaGetSymbolAddress((void**)&p_as2, g_as2);
        cudaGetSymbolAddress((void**)&p_ad2, g_ad2);
        cudaGetSymbolAddress((void**)&p_amax2, g_amax2);
        cudaGetSymbolAddress((void**)&p_den2, g_den2);
        cudaGetSymbolAddress((void**)&p_alpha2, g_alpha2);
        cudaGetSymbolAddress((void**)&p_out2, g_out2);
    }

    const int TB = 256;
    auto blocks = [](int n, int tb) { return (n + tb - 1) / tb; };

    // ---- init accumulators ----
    fill_kernel<<<blocks(NN * H1, TB), TB>>>(p_amax1, -INFINITY, NN * H1);
    fill_kernel<<<blocks(NN * H1, TB), TB>>>(p_den1, 0.f, NN * H1);
    fill_kernel<<<blocks(NN * HC1, TB), TB>>>(p_out1, 0.f, NN * HC1);
    fill_kernel<<<blocks(NN, TB), TB>>>(p_amax2, -INFINITY, NN);
    fill_kernel<<<blocks(NN, TB), TB>>>(p_den2, 0.f, NN);
    fill_kernel<<<blocks(NN * C2, TB), TB>>>(p_out2, 0.f, NN * C2);

    // ---- layer 1 ----
    {
        dim3 grid((HC1 + BN - 1) / BN, (NN + BM - 1) / BM);
        gemm_nt<<<grid, 256>>>(x, W1, p_h1, NN, HC1, NF);
    }
    att_kernel<<<blocks(NN * H1, TB), TB>>>(p_h1, at1s, at1d, p_as1, p_ad1, NN, H1, C1);
    edge_max<<<blocks(EP * H1, TB), TB>>>(ei, p_as1, p_ad1, p_alpha1, p_amax1, E, NN, H1);
    edge_exp<<<blocks(EP * H1, TB), TB>>>(ei, p_alpha1, p_amax1, p_den1, E, NN, H1);
    edge_agg<<<blocks(EP * H1, TB), TB>>>(ei, p_alpha1, p_den1, p_h1, p_out1, E, NN, H1, C1);
    elu_bias<<<blocks(NN * HC1, TB), TB>>>(p_out1, b1, NN * HC1, HC1);

    // ---- layer 2 ----
    {
        dim3 grid((C2 + BN - 1) / BN, (NN + BM - 1) / BM);
        gemm_nt<<<grid, 256>>>(p_out1, W2, p_h2, NN, C2, HC1);
    }
    att_kernel<<<blocks(NN, TB), TB>>>(p_h2, at2s, at2d, p_as2, p_ad2, NN, 1, C2);
    edge_max<<<blocks(EP, TB), TB>>>(ei, p_as2, p_ad2, p_alpha2, p_amax2, E, NN, 1);
    edge_exp<<<blocks(EP, TB), TB>>>(ei, p_alpha2, p_amax2, p_den2, E, NN, 1);
    edge_agg<<<blocks(EP, TB), TB>>>(ei, p_alpha2, p_den2, p_h2, p_out2, E, NN, 1, C2);

    // ---- log_softmax ----
    final_lsm<<<blocks(NN, TB), TB>>>(p_out2, b2, out, NN);
}

// round 2
// speedup vs baseline: 2.1093x; 2.1093x over previous
#include <cuda_runtime.h>
#include <math.h>

// ---------------- problem constants ----------------
#define NN   50000
#define NE   1600000
#define EPAD (NE + NN)        // edges + self loops
#define NF   512
#define H1   8
#define C1   16
#define HC1  128
#define C2   16

// ---------------- scratch (device globals) ----------------
__device__ float g_h1[NN * HC1];
__device__ float g_as1[NN * H1];
__device__ float g_ad1[NN * H1];
__device__ float g_out1[NN * HC1];
__device__ float g_h2[NN * C2];
__device__ float g_as2[NN];
__device__ float g_ad2[NN];
__device__ float g_out2[NN * C2];
__device__ int   g_cnt[NN];
__device__ int   g_rowptr[NN + 1];
__device__ int   g_cursor[NN];
__device__ int   g_col[EPAD];

// ================= CSR build =================
__global__ void fill_int(int* p, int v, int n) {
    int i = blockIdx.x * blockDim.x + threadIdx.x;
    if (i < n) p[i] = v;
}

__global__ void count_dst(const int* __restrict__ ei, int* __restrict__ cnt, int E) {
    int e = blockIdx.x * blockDim.x + threadIdx.x;
    if (e < E) atomicAdd(&cnt[ei[E + e]], 1);
}

// single-block exclusive scan over NN counts -> rowptr[NN+1]
__global__ void scan_rowptr(const int* __restrict__ cnt, int* __restrict__ rowptr) {
    __shared__ int ssum[1024];
    const int T = 1024;
    const int PER = (NN + T - 1) / T;   // 49
    int tid = threadIdx.x;
    int start = tid * PER;
    int local = 0;
    for (int i = 0; i < PER; i++) {
        int idx = start + i;
        if (idx < NN) local += cnt[idx];
    }
    ssum[tid] = local;
    __syncthreads();
    // Hillis-Steele inclusive scan
    for (int off = 1; off < T; off <<= 1) {
        int v = (tid >= off) ? ssum[tid - off] : 0;
        __syncthreads();
        ssum[tid] += v;
        __syncthreads();
    }
    int run = (tid == 0) ? 0 : ssum[tid - 1];
    for (int i = 0; i < PER; i++) {
        int idx = start + i;
        if (idx < NN) { rowptr[idx] = run; run += cnt[idx]; }
    }
    if (tid == T - 1) rowptr[NN] = ssum[T - 1];
}

__global__ void copy_cursor(const int* __restrict__ rowptr, int* __restrict__ cursor) {
    int i = blockIdx.x * blockDim.x + threadIdx.x;
    if (i < NN) cursor[i] = rowptr[i];
}

// scatter E edges + NN self loops into col[]
__global__ void scatter_edges(const int* __restrict__ ei, int* __restrict__ cursor,
                              int* __restrict__ col, int E) {
    int i = blockIdx.x * blockDim.x + threadIdx.x;
    int tot = E + NN;
    if (i >= tot) return;
    int s, d;
    if (i < E) { s = ei[i]; d = ei[E + i]; } else { s = d = i - E; }
    int pos = atomicAdd(&cursor[d], 1);
    col[pos] = s;
}

// ================= SGEMM (NT): C[M,N] = A[M,K]*B[N,K]^T =================
#define GBM 128
#define GBN 128
#define GBK 8

__global__ __launch_bounds__(256, 2)
void gemm_nt(const float* __restrict__ A, const float* __restrict__ B,
             float* __restrict__ C, int M, int Nn, int K) {
    __shared__ float As[GBK][GBM];
    __shared__ float Bs[GBK][GBN];
    int t = threadIdx.x;
    int tx = t & 15, ty = t >> 4;          // 16x16 threads, 8x8 each
    int m0 = blockIdx.y * GBM, n0 = blockIdx.x * GBN;
    int lrow = t >> 1;                      // 0..127
    int lk = (t & 1) * 4;                   // 0 or 4

    float acc[8][8];
    #pragma unroll
    for (int i = 0; i < 8; i++)
        #pragma unroll
        for (int j = 0; j < 8; j++) acc[i][j] = 0.f;

    for (int k0 = 0; k0 < K; k0 += GBK) {
        float4 av = make_float4(0.f, 0.f, 0.f, 0.f);
        float4 bv = make_float4(0.f, 0.f, 0.f, 0.f);
        int am = m0 + lrow;
        if (am < M) av = *reinterpret_cast<const float4*>(&A[(size_t)am * K + k0 + lk]);
        int bn = n0 + lrow;
        if (bn < Nn) bv = *reinterpret_cast<const float4*>(&B[(size_t)bn * K + k0 + lk]);
        As[lk + 0][lrow] = av.x; As[lk + 1][lrow] = av.y;
        As[lk + 2][lrow] = av.z; As[lk + 3][lrow] = av.w;
        Bs[lk + 0][lrow] = bv.x; Bs[lk + 1][lrow] = bv.y;
        Bs[lk + 2][lrow] = bv.z; Bs[lk + 3][lrow] = bv.w;
        __syncthreads();
        #pragma unroll
        for (int k = 0; k < GBK; k++) {
            float a[8], b[8];
            float4 a0 = *reinterpret_cast<const float4*>(&As[k][ty * 8]);
            float4 a1 = *reinterpret_cast<const float4*>(&As[k][ty * 8 + 4]);
            float4 b0 = *reinterpret_cast<const float4*>(&Bs[k][tx * 8]);
            float4 b1 = *reinterpret_cast<const float4*>(&Bs[k][tx * 8 + 4]);
            a[0]=a0.x;a[1]=a0.y;a[2]=a0.z;a[3]=a0.w;a[4]=a1.x;a[5]=a1.y;a[6]=a1.z;a[7]=a1.w;
            b[0]=b0.x;b[1]=b0.y;b[2]=b0.z;b[3]=b0.w;b[4]=b1.x;b[5]=b1.y;b[6]=b1.z;b[7]=b1.w;
            #pragma unroll
            for (int i = 0; i < 8; i++)
                #pragma unroll
                for (int j = 0; j < 8; j++) acc[i][j] += a[i] * b[j];
        }
        __syncthreads();
    }
    #pragma unroll
    for (int i = 0; i < 8; i++) {
        int m = m0 + ty * 8 + i;
        if (m >= M) continue;
        #pragma unroll
        for (int j = 0; j < 8; j++) {
            int n = n0 + tx * 8 + j;
            if (n < Nn) C[(size_t)m * Nn + n] = acc[i][j];
        }
    }
}

// ================= attention coefficients =================
__global__ void att_kernel(const float* __restrict__ h, const float* __restrict__ att_s,
                           const float* __restrict__ att_d, float* __restrict__ as_,
                           float* __restrict__ ad_, int N, int H, int C) {
    int idx = blockIdx.x * blockDim.x + threadIdx.x;
    if (idx >= N * H) return;
    int n = idx / H, hh = idx - n * H;
    const float* hp = h + ((size_t)n * H + hh) * C;
    float s = 0.f, d = 0.f;
    for (int c = 0; c < C; c++) {
        float v = hp[c];
        s += v * att_s[hh * C + c];
        d += v * att_d[hh * C + c];
    }
    as_[idx] = s;
    ad_[idx] = d;
}

// ================= fused GAT aggregate: one warp per (dst, head) =================
// C must be 16. APPLY_ELU: fuse bias+ELU (layer 1). bias layout [H*C].
template<int H, bool APPLY_ELU>
__global__ void gat_aggregate(const int* __restrict__ rowptr, const int* __restrict__ col,
                              const float* __restrict__ as_, const float* __restrict__ ad_,
                              const float* __restrict__ hfeat, const float* __restrict__ bias,
                              float* __restrict__ out) {
    const int C = 16;
    int gw = (blockIdx.x * blockDim.x + threadIdx.x) >> 5;
    int lane = threadIdx.x & 31;
    if (gw >= NN * H) return;
    int dst = gw / H, head = gw - dst * H;

    int beg = rowptr[dst], end = rowptr[dst + 1];
    float adv = ad_[dst * H + head];

    // pass 1: max
    float m = -INFINITY;
    for (int i = beg + lane; i < end; i += 32) {
        float v = as_[col[i] * H + head] + adv;
        v = v > 0.f ? v : 0.2f * v;
        m = fmaxf(m, v);
    }
    #pragma unroll
    for (int o = 16; o > 0; o >>= 1) m = fmaxf(m, __shfl_xor_sync(0xffffffffu, m, o));

    // pass 2: sum of exp
    float s = 0.f;
    for (int i = beg + lane; i < end; i += 32) {
        float v = as_[col[i] * H + head] + adv;
        v = v > 0.f ? v : 0.2f * v;
        s += __expf(v - m);
    }
    #pragma unroll
    for (int o = 16; o > 0; o >>= 1) s += __shfl_xor_sync(0xffffffffu, s, o);

    // pass 3: weighted aggregate; 2 edges per iter, 16 channels each
    int c = lane & 15;
    int sub = lane >> 4;
    float acc = 0.f;
    for (int i = beg + sub; i < end; i += 2) {
        int src = col[i];
        float v = as_[src * H + head] + adv;
        v = v > 0.f ? v : 0.2f * v;
        float w = __expf(v - m);
        acc += w * hfeat[((size_t)src * H + head) * C + c];
    }
    acc += __shfl_down_sync(0xffffffffu, acc, 16);
    if (lane < 16) {
        float r = acc / (s + 1e-16f);
        if (APPLY_ELU) {
            r += bias[head * C + c];
            r = r > 0.f ? r : expm1f(r);
        }
        out[((size_t)dst * H + head) * C + c] = r;
    }
}

// ================= final bias + log_softmax =================
__global__ void final_lsm(const float* __restrict__ in, const float* __restrict__ b,
                          float* __restrict__ out, int N) {
    int n = blockIdx.x * blockDim.x + threadIdx.x;
    if (n >= N) return;
    float v[C2];
    float m = -INFINITY;
    #pragma unroll
    for (int c = 0; c < C2; c++) {
        v[c] = in[(size_t)n * C2 + c] + b[c];
        m = fmaxf(m, v[c]);
    }
    float s = 0.f;
    #pragma unroll
    for (int c = 0; c < C2; c++) s += __expf(v[c] - m);
    float l = __logf(s);
    #pragma unroll
    for (int c = 0; c < C2; c++) out[(size_t)n * C2 + c] = v[c] - m - l;
}

// ================= launch =================
extern "C" void kernel_launch(void* const* d_in, const int* in_sizes, int n_in,
                              void* d_out, int out_size) {
    const float* x    = (const float*)d_in[0];
    const int*   ei   = (const int*)d_in[1];
    const float* W1   = (const float*)d_in[2];
    const float* at1s = (const float*)d_in[3];
    const float* at1d = (const float*)d_in[4];
    const float* b1   = (const float*)d_in[5];
    const float* W2   = (const float*)d_in[6];
    const float* at2s = (const float*)d_in[7];
    const float* at2d = (const float*)d_in[8];
    const float* b2   = (const float*)d_in[9];
    float* out = (float*)d_out;

    int E = in_sizes[1] / 2;

    static float *p_h1 = nullptr, *p_as1, *p_ad1, *p_out1, *p_h2, *p_as2, *p_ad2, *p_out2;
    static int *p_cnt, *p_rowptr, *p_cursor, *p_col;
    if (!p_h1) {
        cudaGetSymbolAddress((void**)&p_h1, g_h1);
        cudaGetSymbolAddress((void**)&p_as1, g_as1);
        cudaGetSymbolAddress((void**)&p_ad1, g_ad1);
        cudaGetSymbolAddress((void**)&p_out1, g_out1);
        cudaGetSymbolAddress((void**)&p_h2, g_h2);
        cudaGetSymbolAddress((void**)&p_as2, g_as2);
        cudaGetSymbolAddress((void**)&p_ad2, g_ad2);
        cudaGetSymbolAddress((void**)&p_out2, g_out2);
        cudaGetSymbolAddress((void**)&p_cnt, g_cnt);
        cudaGetSymbolAddress((void**)&p_rowptr, g_rowptr);
        cudaGetSymbolAddress((void**)&p_cursor, g_cursor);
        cudaGetSymbolAddress((void**)&p_col, g_col);
    }

    const int TB = 256;
    auto blocks = [](int n, int tb) { return (n + tb - 1) / tb; };

    // ---- CSR build (shared by both layers) ----
    fill_int<<<blocks(NN, TB), TB>>>(p_cnt, 1, NN);                 // 1 = self loop
    count_dst<<<blocks(E, TB), TB>>>(ei, p_cnt, E);
    scan_rowptr<<<1, 1024>>>(p_cnt, p_rowptr);
    copy_cursor<<<blocks(NN, TB), TB>>>(p_rowptr, p_cursor);
    scatter_edges<<<blocks(E + NN, TB), TB>>>(ei, p_cursor, p_col, E);

    // ---- layer 1 ----
    {
        dim3 grid((HC1 + GBN - 1) / GBN, (NN + GBM - 1) / GBM);
        gemm_nt<<<grid, 256>>>(x, W1, p_h1, NN, HC1, NF);
    }
    att_kernel<<<blocks(NN * H1, TB), TB>>>(p_h1, at1s, at1d, p_as1, p_ad1, NN, H1, C1);
    gat_aggregate<H1, true><<<blocks(NN * H1 * 32, TB), TB>>>(
        p_rowptr, p_col, p_as1, p_ad1, p_h1, b1, p_out1);

    // ---- layer 2 ----
    {
        dim3 grid((C2 + GBN - 1) / GBN, (NN + GBM - 1) / GBM);
        gemm_nt<<<grid, 256>>>(p_out1, W2, p_h2, NN, C2, HC1);
    }
    att_kernel<<<blocks(NN, TB), TB>>>(p_h2, at2s, at2d, p_as2, p_ad2, NN, 1, C2);
    gat_aggregate<1, false><<<blocks(NN * 32, TB), TB>>>(
        p_rowptr, p_col, p_as2, p_ad2, p_h2, nullptr, p_out2);

    // ---- log_softmax ----
    final_lsm<<<blocks(NN, TB), TB>>>(p_out2, b2, out, NN);
}